// round 7
// baseline (speedup 1.0000x reference)
#include <cuda_runtime.h>
#include <math_constants.h>

#define FULL_MASK 0xFFFFFFFFu
#define INF_BITS  0x7f800000u

// x: (32, 2, 513, 2048) fp32. channel 0 = magnitude, channel 1 = phase.
// rows = 32*513 = 16416, row length 2048. One warp per row-task, no smem.
// R7: single-wave launch. 1026 blocks x 4 warps = 4104 warps, each does exactly
// 4 rows (4104*4 = 16416). 1026 <= 148 SMs * 8 resident blocks -> one wave,
// no wave-quantization tail (R4/R6 ran 3.47 waves; ~13% idle in the last wave).
// Row body identical to R4/R6 (proven 88.2us @ DRAM 76%).

// Branchless insert into sorted list a0<=...<=a5 (keep 6 smallest).
#define INS6(a0,a1,a2,a3,a4,a5,sv) do { float s_ = (sv); \
    a5 = fminf(a5, fmaxf(a4, s_));                       \
    a4 = fminf(a4, fmaxf(a3, s_));                       \
    a3 = fminf(a3, fmaxf(a2, s_));                       \
    a2 = fminf(a2, fmaxf(a1, s_));                       \
    a1 = fminf(a1, fmaxf(a0, s_));                       \
    a0 = fminf(a0, s_); } while (0)

#define INSA(sv) INS6(m0,m1,m2,m3,m4,m5,sv)
#define INSB(sv) INS6(n0,n1,n2,n3,n4,n5,sv)

__global__ __launch_bounds__(128, 8)   // <=64 regs -> 8 blocks -> 32 warps/SM
void spectral_sub_kernel(const float* __restrict__ x, float* __restrict__ out)
{
    const int lane = threadIdx.x & 31;
    const int warp = threadIdx.x >> 5;
    const int wid  = blockIdx.x * 4 + warp;          // [0, 4104)

    #pragma unroll 1
    for (int j = 0; j < 4; ++j) {
        const int row = wid * 4 + j;                 // [0, 16416)

        const int b = row / 513;
        const int f = row - b * 513;
        const size_t moff = (size_t)(b * 1026 + f) * 2048;   // ((b*2+0)*513+f)*2048
        const float4* __restrict__ magv = (const float4*)(x + moff);
        const float4* __restrict__ phv  = (const float4*)(x + moff + (size_t)513 * 2048);
        float4* __restrict__ outr = (float4*)(out + moff);
        float4* __restrict__ outi = (float4*)(out + moff + (size_t)513 * 2048);

        // ---- Phase A: two independent per-lane sorted-6 lists over squares ----
        float m0 = CUDART_INF_F, m1 = CUDART_INF_F, m2 = CUDART_INF_F,
              m3 = CUDART_INF_F, m4 = CUDART_INF_F, m5 = CUDART_INF_F;
        float n0 = CUDART_INF_F, n1 = CUDART_INF_F, n2 = CUDART_INF_F,
              n3 = CUDART_INF_F, n4 = CUDART_INF_F, n5 = CUDART_INF_F;

        #pragma unroll
        for (int h = 0; h < 2; ++h) {
            float4 d[8];
            #pragma unroll
            for (int c = 0; c < 8; ++c)               // 8 LDG.128 batched (MLP=8)
                d[c] = magv[(h * 8 + c) * 32 + lane];
            #pragma unroll
            for (int c = 0; c < 8; c += 2) {
                float4 a = d[c], e = d[c + 1];        // two independent chains
                INSA(a.x * a.x);  INSB(e.x * e.x);
                INSA(a.y * a.y);  INSB(e.y * e.y);
                INSA(a.z * a.z);  INSB(e.z * e.z);
                INSA(a.w * a.w);  INSB(e.w * e.w);
            }
        }
        // merge list B into A -> A holds this lane's 6 smallest squares
        INSA(n0); INSA(n1); INSA(n2); INSA(n3); INSA(n4); INSA(n5);

        // ---- prefetch pass-2 batch 0 (hidden behind the extraction chain) ----
        float4 pm[4], pp[4];
        #pragma unroll
        for (int c = 0; c < 4; ++c) {
            pm[c] = magv[c * 32 + lane];
            pp[c] = __ldcs(&phv[c * 32 + lane]);
        }

        // ---- extraction: 32 ascending pops of the warp-wide minimum ----
        float sum = 0.0f;
        #pragma unroll 1
        for (int iter = 0; iter < 32; ++iter) {
            unsigned u = __float_as_uint(m0);
            unsigned w = __reduce_min_sync(FULL_MASK, u);     // REDUX.MIN
            sum += __uint_as_float(w);
            unsigned bal = __ballot_sync(FULL_MASK, u == w);  // one pop per iter
            if (lane == __ffs(bal) - 1) {
                m0 = m1; m1 = m2; m2 = m3; m3 = m4; m4 = m5; m5 = CUDART_INF_F;
                if (__float_as_uint(m0) == INF_BITS) {
                    // exact rebuild (~1.2% of rows): next-6 of this lane > t.
                    const float t = __uint_as_float(w);
                    #pragma unroll
                    for (int c = 0; c < 16; ++c) {
                        float4 dv = magv[c * 32 + lane];      // L2-hot reload
                        float s;
                        s = dv.x * dv.x; s = (s > t) ? s : CUDART_INF_F; INSA(s);
                        s = dv.y * dv.y; s = (s > t) ? s : CUDART_INF_F; INSA(s);
                        s = dv.z * dv.z; s = (s > t) ? s : CUDART_INF_F; INSA(s);
                        s = dv.w * dv.w; s = (s > t) ? s : CUDART_INF_F; INSA(s);
                    }
                }
            }
        }
        const float noise = sum * (1.0f / 32.0f);

        // ---- Pass 2: mag re-read (L2-hot) + streamed phase -> real/imag ----
        #pragma unroll
        for (int s = 0; s < 4; ++s) {
            float4 mm[4], ph[4];
            if (s == 0) {
                #pragma unroll
                for (int c = 0; c < 4; ++c) { mm[c] = pm[c]; ph[c] = pp[c]; }
            } else {
                #pragma unroll
                for (int c = 0; c < 4; ++c) {         // 8 LDGs batched (MLP=8)
                    mm[c] = magv[(s * 4 + c) * 32 + lane];
                    ph[c] = __ldcs(&phv[(s * 4 + c) * 32 + lane]);
                }
            }
            #pragma unroll
            for (int c = 0; c < 4; ++c) {
                float4 re, im;
                float m, sn, cs;
                m = fmaxf(mm[c].x - noise, 0.0f); __sincosf(ph[c].x, &sn, &cs); re.x = m*cs; im.x = m*sn;
                m = fmaxf(mm[c].y - noise, 0.0f); __sincosf(ph[c].y, &sn, &cs); re.y = m*cs; im.y = m*sn;
                m = fmaxf(mm[c].z - noise, 0.0f); __sincosf(ph[c].z, &sn, &cs); re.z = m*cs; im.z = m*sn;
                m = fmaxf(mm[c].w - noise, 0.0f); __sincosf(ph[c].w, &sn, &cs); re.w = m*cs; im.w = m*sn;
                __stcs(&outr[(s * 4 + c) * 32 + lane], re);
                __stcs(&outi[(s * 4 + c) * 32 + lane], im);
            }
        }
    }
}

extern "C" void kernel_launch(void* const* d_in, const int* in_sizes, int n_in,
                              void* d_out, int out_size)
{
    const float* x = (const float*)d_in[0];
    // d_in[1] = n_avg (int32, fixed at 32 for this problem; algorithm specialized for k==32)
    float* out = (float*)d_out;

    // Single wave: 1026 blocks x 4 warps x 4 rows = 16416 rows
    spectral_sub_kernel<<<1026, 128>>>(x, out);
}

// round 8
// speedup vs baseline: 1.1298x; 1.1298x over previous
#include <cuda_runtime.h>
#include <math_constants.h>

#define FULL_MASK 0xFFFFFFFFu
#define INF_BITS  0x7f800000u

// x: (32, 2, 513, 2048) fp32. channel 0 = magnitude, channel 1 = phase.
// rows = 32*513 = 16416, row length 2048.
// R8: one row per 64-thread block (2 warps cooperate). Each warp runs phase A
// on its half-row; warp1 passes its per-lane sorted-6 via smem; warp0 merges
// and extracts (REDUX.MIN, exact rebuild over the FULL lane column). Halved
// task duration -> 6.93 waves of 2368 block-slots -> ~1% wave-quantization
// idle (R4: 13.3%). Same 32 warps/SM residency, same minimal traffic.

// Branchless insert into sorted list a0<=...<=a5 (keep 6 smallest).
#define INS6(a0,a1,a2,a3,a4,a5,sv) do { float s_ = (sv); \
    a5 = fminf(a5, fmaxf(a4, s_));                       \
    a4 = fminf(a4, fmaxf(a3, s_));                       \
    a3 = fminf(a3, fmaxf(a2, s_));                       \
    a2 = fminf(a2, fmaxf(a1, s_));                       \
    a1 = fminf(a1, fmaxf(a0, s_));                       \
    a0 = fminf(a0, s_); } while (0)

#define INSA(sv) INS6(m0,m1,m2,m3,m4,m5,sv)
#define INSB(sv) INS6(n0,n1,n2,n3,n4,n5,sv)

__global__ __launch_bounds__(64, 16)   // <=64 regs -> 16 blocks -> 32 warps/SM
void spectral_sub_kernel(const float* __restrict__ x, float* __restrict__ out)
{
    __shared__ float s_lists[6][32];   // warp1's per-lane sorted-6
    __shared__ float s_noise;

    const int lane = threadIdx.x & 31;
    const int warp = threadIdx.x >> 5;           // 0 or 1
    const int row  = blockIdx.x;                 // [0, 16416)

    const int b = row / 513;
    const int f = row - b * 513;
    const size_t moff = (size_t)(b * 1026 + f) * 2048;   // ((b*2+0)*513+f)*2048
    const float4* __restrict__ magv = (const float4*)(x + moff);
    const float4* __restrict__ phv  = (const float4*)(x + moff + (size_t)513 * 2048);
    float4* __restrict__ outr = (float4*)(out + moff);
    float4* __restrict__ outi = (float4*)(out + moff + (size_t)513 * 2048);

    const int base = warp * 8;                   // this warp's half: float4 idx [base, base+8)

    // ---- Phase A: per-lane sorted-6 over this warp's 32 values/lane ----
    float m0 = CUDART_INF_F, m1 = CUDART_INF_F, m2 = CUDART_INF_F,
          m3 = CUDART_INF_F, m4 = CUDART_INF_F, m5 = CUDART_INF_F;
    float n0 = CUDART_INF_F, n1 = CUDART_INF_F, n2 = CUDART_INF_F,
          n3 = CUDART_INF_F, n4 = CUDART_INF_F, n5 = CUDART_INF_F;
    {
        float4 d[8];
        #pragma unroll
        for (int c = 0; c < 8; ++c)               // 8 LDG.128 batched (MLP=8)
            d[c] = magv[(base + c) * 32 + lane];
        #pragma unroll
        for (int c = 0; c < 4; ++c) {             // two independent chains
            float4 a = d[c], e = d[c + 4];
            INSA(a.x * a.x);  INSB(e.x * e.x);
            INSA(a.y * a.y);  INSB(e.y * e.y);
            INSA(a.z * a.z);  INSB(e.z * e.z);
            INSA(a.w * a.w);  INSB(e.w * e.w);
        }
        INSA(n0); INSA(n1); INSA(n2); INSA(n3); INSA(n4); INSA(n5);
    }

    if (warp == 1) {
        s_lists[0][lane] = m0; s_lists[1][lane] = m1; s_lists[2][lane] = m2;
        s_lists[3][lane] = m3; s_lists[4][lane] = m4; s_lists[5][lane] = m5;
    }
    __syncthreads();

    // ---- prefetch own half's pass-2 batch 0 (in flight during extraction) ----
    float4 pm[4], pp[4];
    #pragma unroll
    for (int c = 0; c < 4; ++c) {
        pm[c] = magv[(base + c) * 32 + lane];
        pp[c] = __ldcs(&phv[(base + c) * 32 + lane]);
    }

    if (warp == 0) {
        // merge warp1's lists: lane slot i now covers the FULL row column i
        INSA(s_lists[0][lane]); INSA(s_lists[1][lane]); INSA(s_lists[2][lane]);
        INSA(s_lists[3][lane]); INSA(s_lists[4][lane]); INSA(s_lists[5][lane]);

        // ---- extraction: 32 ascending pops of the warp-wide minimum ----
        float sum = 0.0f;
        #pragma unroll 1
        for (int iter = 0; iter < 32; ++iter) {
            unsigned u = __float_as_uint(m0);      // squares >=0: bit-order == value-order
            unsigned w = __reduce_min_sync(FULL_MASK, u);     // REDUX.MIN
            sum += __uint_as_float(w);
            unsigned bal = __ballot_sync(FULL_MASK, u == w);  // one pop per iter
            if (lane == __ffs(bal) - 1) {
                m0 = m1; m1 = m2; m2 = m3; m3 = m4; m4 = m5; m5 = CUDART_INF_F;
                if (__float_as_uint(m0) == INF_BITS) {
                    // exact rebuild (rare): next-6 of this lane's FULL column > t
                    const float t = __uint_as_float(w);
                    #pragma unroll
                    for (int c = 0; c < 16; ++c) {
                        float4 dv = magv[c * 32 + lane];      // L2-hot reload
                        float s;
                        s = dv.x * dv.x; s = (s > t) ? s : CUDART_INF_F; INSA(s);
                        s = dv.y * dv.y; s = (s > t) ? s : CUDART_INF_F; INSA(s);
                        s = dv.z * dv.z; s = (s > t) ? s : CUDART_INF_F; INSA(s);
                        s = dv.w * dv.w; s = (s > t) ? s : CUDART_INF_F; INSA(s);
                    }
                }
            }
        }
        if (lane == 0) s_noise = sum * (1.0f / 32.0f);
    }
    __syncthreads();
    const float noise = s_noise;

    // ---- Pass 2 on own half: mag re-read (L2-hot) + streamed phase ----
    #pragma unroll
    for (int s = 0; s < 2; ++s) {
        float4 mm[4], ph[4];
        if (s == 0) {
            #pragma unroll
            for (int c = 0; c < 4; ++c) { mm[c] = pm[c]; ph[c] = pp[c]; }
        } else {
            #pragma unroll
            for (int c = 0; c < 4; ++c) {             // 8 LDGs batched (MLP=8)
                mm[c] = magv[(base + 4 + c) * 32 + lane];
                ph[c] = __ldcs(&phv[(base + 4 + c) * 32 + lane]);
            }
        }
        #pragma unroll
        for (int c = 0; c < 4; ++c) {
            const int o = (base + s * 4 + c) * 32 + lane;
            float4 re, im;
            float m, sn, cs;
            m = fmaxf(mm[c].x - noise, 0.0f); __sincosf(ph[c].x, &sn, &cs); re.x = m*cs; im.x = m*sn;
            m = fmaxf(mm[c].y - noise, 0.0f); __sincosf(ph[c].y, &sn, &cs); re.y = m*cs; im.y = m*sn;
            m = fmaxf(mm[c].z - noise, 0.0f); __sincosf(ph[c].z, &sn, &cs); re.z = m*cs; im.z = m*sn;
            m = fmaxf(mm[c].w - noise, 0.0f); __sincosf(ph[c].w, &sn, &cs); re.w = m*cs; im.w = m*sn;
            __stcs(&outr[o], re);
            __stcs(&outi[o], im);
        }
    }
}

extern "C" void kernel_launch(void* const* d_in, const int* in_sizes, int n_in,
                              void* d_out, int out_size)
{
    const float* x = (const float*)d_in[0];
    // d_in[1] = n_avg (int32, fixed at 32 for this problem; algorithm specialized for k==32)
    float* out = (float*)d_out;

    // one row per 64-thread block: 16416 blocks, ~6.93 waves of 2368 slots (~1% tail)
    spectral_sub_kernel<<<16416, 64>>>(x, out);
}